// round 6
// baseline (speedup 1.0000x reference)
#include <cuda_runtime.h>
#include <cuda_fp16.h>
#include <stdint.h>

#define B_ 4
#define L_ 4096
#define D_ 512
#define M_ (B_*L_)

// ---------------- device scratch ---------------------------------------------
__device__ __half g_x16[(size_t)M_*D_];
__device__ __half g_Wq16[D_*D_], g_Wk16[D_*D_];
__device__ __half g_Q[(size_t)M_*D_], g_K[(size_t)M_*D_];
__device__ float g_colw[B_*L_];
__device__ float g_t[B_*D_];

// ---------------- helpers ----------------------------------------------------
#define SWZ(o) ((o) ^ ((((uint32_t)(o))>>3)&0x70u))

__device__ __forceinline__ uint32_t smem_u32(const void* p){
    return (uint32_t)__cvta_generic_to_shared(p);
}
__device__ __forceinline__ void ldsm4(uint32_t* r, uint32_t a){
    asm volatile("ldmatrix.sync.aligned.m8n8.x4.shared.b16 {%0,%1,%2,%3}, [%4];"
        : "=r"(r[0]), "=r"(r[1]), "=r"(r[2]), "=r"(r[3]) : "r"(a));
}
__device__ __forceinline__ void mma16816(float* d, const uint32_t* a, uint32_t b0, uint32_t b1){
    asm volatile("mma.sync.aligned.m16n8k16.row.col.f32.f16.f16.f32 "
        "{%0,%1,%2,%3}, {%4,%5,%6,%7}, {%8,%9}, {%0,%1,%2,%3};"
        : "+f"(d[0]), "+f"(d[1]), "+f"(d[2]), "+f"(d[3])
        : "r"(a[0]), "r"(a[1]), "r"(a[2]), "r"(a[3]), "r"(b0), "r"(b1));
}
__device__ __forceinline__ void mma16816h(uint32_t* d, const uint32_t* a, uint32_t b0, uint32_t b1){
    asm volatile("mma.sync.aligned.m16n8k16.row.col.f16.f16.f16.f16 "
        "{%0,%1}, {%2,%3,%4,%5}, {%6,%7}, {%0,%1};"
        : "+r"(d[0]), "+r"(d[1])
        : "r"(a[0]), "r"(a[1]), "r"(a[2]), "r"(a[3]), "r"(b0), "r"(b1));
}
__device__ __forceinline__ void cpa16(uint32_t s, const void* g){
    asm volatile("cp.async.cg.shared.global [%0], [%1], 16;" :: "r"(s), "l"(g) : "memory");
}
#define CP_COMMIT() asm volatile("cp.async.commit_group;" ::: "memory")
#define CP_WAIT(n)  asm volatile("cp.async.wait_group %0;" :: "n"(n) : "memory")

// packed subtile offset: 64 rows x 32 halfs stored as 32 x 128B smem rows
__device__ __forceinline__ uint32_t pko(int r, int seg){
    return ((uint32_t)(r>>1)<<7) + ((uint32_t)(r&1)<<6) + (uint32_t)seg*16;
}

// ---------------- prep (convert x, Wq, Wk; zero accumulators) ------------------
__global__ void prep_kernel(const float* __restrict__ x,
                            const float* __restrict__ Wq,
                            const float* __restrict__ Wk){
    int i = blockIdx.x*256 + threadIdx.x;       // 0 .. 2M-1 (float4 index of x)
    float4 v = ((const float4*)x)[i];
    ((__half2*)g_x16)[i*2]   = __floats2half2_rn(v.x, v.y);
    ((__half2*)g_x16)[i*2+1] = __floats2half2_rn(v.z, v.w);
    if (i < D_*D_/4){
        float4 a = ((const float4*)Wq)[i];
        float4 b = ((const float4*)Wk)[i];
        ((__half2*)g_Wq16)[i*2]   = __floats2half2_rn(a.x, a.y);
        ((__half2*)g_Wq16)[i*2+1] = __floats2half2_rn(a.z, a.w);
        ((__half2*)g_Wk16)[i*2]   = __floats2half2_rn(b.x, b.y);
        ((__half2*)g_Wk16)[i*2+1] = __floats2half2_rn(b.z, b.w);
    }
    if (i < B_*L_) g_colw[i] = 0.f;
    if (i < B_*D_) g_t[i] = 0.f;
}

// ---------------- projection GEMM (HMMA, unchanged from r5) --------------------
#define PJ_STAGE 32768
#define PJ_SMEM  (2*PJ_STAGE)

__device__ __forceinline__ void pj_load(const __half* __restrict__ A,
                                        const __half* __restrict__ W,
                                        int m0, int n0, int kc, uint32_t sdst, int tid){
#pragma unroll
    for (int i = 0; i < 8; i++){
        int lin = i*256 + tid;
        int sub = lin >> 9, row = (lin >> 3) & 63, sec = lin & 7;
        const __half* src;
        if (sub < 2) src = A + (size_t)(m0 + sub*64 + row)*D_ + kc + sec*8;
        else         src = W + (size_t)(n0 + (sub-2)*64 + row)*D_ + kc + sec*8;
        cpa16(sdst + sub*8192 + SWZ(row*128 + sec*16), src);
    }
}

__global__ __launch_bounds__(256, 1)
void proj_hmma(const __half* __restrict__ A,
               const __half* __restrict__ W0, const __half* __restrict__ W1,
               __half* __restrict__ C0, __half* __restrict__ C1){
    extern __shared__ __align__(1024) char sm[];
    const __half* W = blockIdx.z ? W1 : W0;
    __half* C = blockIdx.z ? C1 : C0;
    const int tid = threadIdx.x, wid = tid >> 5, lane = tid & 31;
    const int m0 = blockIdx.y * 128, n0 = blockIdx.x * 128;
    const uint32_t sb = smem_u32(sm);

    const int mw = (wid & 3) * 32, nw = (wid >> 2) * 64;
    const int a_r = lane & 15, a_s = (lane >> 4) * 16;
    const int b_n = (lane & 7) + ((lane >> 4) << 3);
    const int b_s = ((lane >> 3) & 1) * 16;

    float acc[2][8][4];
#pragma unroll
    for (int i = 0; i < 2; i++)
#pragma unroll
        for (int j = 0; j < 8; j++)
#pragma unroll
            for (int v = 0; v < 4; v++) acc[i][j][v] = 0.f;

    pj_load(A, W, m0, n0, 0, sb, tid); CP_COMMIT();

    for (int c = 0; c < 8; c++){
        if (c < 7){ pj_load(A, W, m0, n0, (c+1)*64, sb + ((c+1)&1)*PJ_STAGE, tid);
                    CP_COMMIT(); CP_WAIT(1); }
        else      { CP_WAIT(0); }
        __syncthreads();
        uint32_t st = sb + (c & 1) * PJ_STAGE;
#pragma unroll
        for (int ks = 0; ks < 4; ks++){
            int kb = ks * 32;
            uint32_t A0[4], A1[4], Bv[4];
            {
                int r0 = mw + a_r, r1 = mw + 16 + a_r;
                ldsm4(A0, st + (r0 >> 6)*8192 + SWZ((r0 & 63)*128 + kb + a_s));
                ldsm4(A1, st + (r1 >> 6)*8192 + SWZ((r1 & 63)*128 + kb + a_s));
            }
#pragma unroll
            for (int nb = 0; nb < 4; nb++){
                int n = nw + nb*16 + b_n;
                ldsm4(Bv, st + (2 + (n >> 6))*8192 + SWZ((n & 63)*128 + kb + b_s));
                mma16816(acc[0][nb*2],   A0, Bv[0], Bv[1]);
                mma16816(acc[0][nb*2+1], A0, Bv[2], Bv[3]);
                mma16816(acc[1][nb*2],   A1, Bv[0], Bv[1]);
                mma16816(acc[1][nb*2+1], A1, Bv[2], Bv[3]);
            }
        }
        __syncthreads();
    }

    const int er = lane >> 2, ec = (lane & 3) * 2;
#pragma unroll
    for (int mt = 0; mt < 2; mt++)
#pragma unroll
        for (int n8 = 0; n8 < 8; n8++){
            size_t r = (size_t)(m0 + mw + mt*16 + er);
            int col = n0 + nw + n8*8 + ec;
            *(__half2*)&C[r*D_ + col] =
                __floats2half2_rn(acc[mt][n8][0], acc[mt][n8][1]);
            *(__half2*)&C[(r+8)*D_ + col] =
                __floats2half2_rn(acc[mt][n8][2], acc[mt][n8][3]);
        }
}

// ---------------- fused scores: 128q x 128k x 4b, warp = 64q x 64k x 1b --------
#define ST_STAGE 65536
#define PARK_OFF (2*ST_STAGE)                    // 131072
#define QS 132                                   // park q-stride (floats)
#define RED_OFF  (PARK_OFF + 4*32*QS*4)          // 131072 + 67584 = 198656
#define SC_SMEM  (RED_OFF + 2048)                // 200704

__device__ __forceinline__ void sc_load(const __half* __restrict__ Q,
                                        const __half* __restrict__ K,
                                        int q0, int k0, int kc, uint32_t sdst, int tid){
#pragma unroll
    for (int i = 0; i < 8; i++){
        int lin = i*512 + tid;                   // 0..4095
        int sub = lin >> 8, rem = lin & 255;
        int r = rem >> 2, seg = rem & 3;
        const __half* src;
        if (sub < 8){
            int b = sub >> 1;
            src = Q + (size_t)(b*L_ + q0 + (sub & 1)*64 + r)*D_ + kc + seg*8;
        } else {
            int s2 = sub - 8, b = s2 >> 1;
            src = K + (size_t)(b*L_ + k0 + (s2 & 1)*64 + r)*D_ + kc + seg*8;
        }
        cpa16(sdst + sub*4096 + SWZ(pko(r, seg)), src);
    }
}

__global__ __launch_bounds__(512, 1)
void scores_hmma(const __half* __restrict__ Q, const __half* __restrict__ K,
                 const int* __restrict__ lens, float* __restrict__ colw){
    extern __shared__ __align__(1024) char sm[];
    const int tid = threadIdx.x, wid = tid >> 5, lane = tid & 31;
    const int q0 = blockIdx.y * 128, k0 = blockIdx.x * 128;
    const uint32_t sb = smem_u32(sm);
    float* Sp  = (float*)(sm + PARK_OFF);
    float* red = (float*)(sm + RED_OFF);
    red[tid] = 0.f;

    const int b  = wid & 3;                      // batch
    const int wq = (wid >> 2) & 1;               // q half (64 rows)
    const int wk = wid >> 3;                     // k half (64 cols)
    const int a_r = lane & 15, a_hi = lane >> 4;
    const int b_n = (lane & 7) + ((lane >> 4) << 3);
    const int b_hi = (lane >> 3) & 1;
    const int er = lane >> 2, ec = (lane & 3) * 2;

    uint32_t acc[4][8][2];                       // fp16x2: [m16 tile][n8 tile][rowhalf]
#pragma unroll
    for (int i = 0; i < 4; i++)
#pragma unroll
        for (int j = 0; j < 8; j++){ acc[i][j][0] = 0u; acc[i][j][1] = 0u; }

    sc_load(Q, K, q0, k0, 0, sb, tid); CP_COMMIT();

    for (int c = 0; c < 16; c++){
        if (c < 15){ sc_load(Q, K, q0, k0, (c+1)*32, sb + ((c+1)&1)*ST_STAGE, tid);
                     CP_COMMIT(); CP_WAIT(1); }
        else       { CP_WAIT(0); }
        __syncthreads();
        uint32_t st = sb + (c & 1)*ST_STAGE;
        uint32_t qt = st + (b*2 + wq)*4096;
        uint32_t kt = st + (8 + b*2 + wk)*4096;
#pragma unroll
        for (int ks = 0; ks < 2; ks++){
            uint32_t Af[4][4];
#pragma unroll
            for (int mt = 0; mt < 4; mt++)
                ldsm4(Af[mt], qt + SWZ(pko(mt*16 + a_r, ks*2 + a_hi)));
#pragma unroll
            for (int nb = 0; nb < 4; nb++){
                uint32_t Bv[4];
                ldsm4(Bv, kt + SWZ(pko(nb*16 + b_n, ks*2 + b_hi)));
#pragma unroll
                for (int mt = 0; mt < 4; mt++){
                    mma16816h(acc[mt][nb*2],   Af[mt], Bv[0], Bv[1]);
                    mma16816h(acc[mt][nb*2+1], Af[mt], Bv[2], Bv[3]);
                }
            }
        }
        __syncthreads();
    }

    // ---------------- epilogue: 4 k-slice passes --------------------------------
    const int le0 = lens[0], le1 = lens[1], le2 = lens[2], le3 = lens[3];
    const int rr = lane & 3, gg = lane >> 2;
    const int sc_rd = gg + 8*rr;                 // this thread's slice column
#pragma unroll
    for (int p = 0; p < 4; p++){
        // park: warp's n16 group p (k cols wk*64 + p*16 .. +15), k-major stride QS
#pragma unroll
        for (int mt = 0; mt < 4; mt++)
#pragma unroll
            for (int tt = 0; tt < 2; tt++){
                int t = p*2 + tt;
#pragma unroll
                for (int rh = 0; rh < 2; rh++){
                    float2 f = __half22float2(*(__half2*)&acc[mt][t][rh]);
                    int qrow = wq*64 + mt*16 + rh*8 + er;
                    int scb  = wk*16 + tt*8 + ec;
                    Sp[(b*32 + scb    )*QS + qrow] = f.x;
                    Sp[(b*32 + scb + 1)*QS + qrow] = f.y;
                }
            }
        __syncthreads();
        // softmax over batch + masked q-sum for this slice
        {
            float a0 = 0.f, a1 = 0.f, a2 = 0.f, a3 = 0.f;
#pragma unroll
            for (int j = 0; j < 8; j++){
                int q = wid*8 + ((j + rr) & 7);
                float s0 = Sp[(0*32 + sc_rd)*QS + q];
                float s1 = Sp[(1*32 + sc_rd)*QS + q];
                float s2 = Sp[(2*32 + sc_rd)*QS + q];
                float s3 = Sp[(3*32 + sc_rd)*QS + q];
                float e0 = __expf(s0 * 0.0625f);
                float e1 = __expf(s1 * 0.0625f);
                float e2 = __expf(s2 * 0.0625f);
                float e3 = __expf(s3 * 0.0625f);
                float inv = 1.f / (e0 + e1 + e2 + e3);
                int qg = q0 + q;
                if (qg < le0) a0 += e0 * inv;
                if (qg < le1) a1 += e1 * inv;
                if (qg < le2) a2 += e2 * inv;
                if (qg < le3) a3 += e3 * inv;
            }
            int kl = (sc_rd >> 4)*64 + p*16 + (sc_rd & 15);
            atomicAdd(&red[kl*4 + 0], a0);
            atomicAdd(&red[kl*4 + 1], a1);
            atomicAdd(&red[kl*4 + 2], a2);
            atomicAdd(&red[kl*4 + 3], a3);
        }
        __syncthreads();
    }
    // flush block partials to global
    {
        int kl = tid >> 2, bb = tid & 3;
        atomicAdd(&colw[bb*L_ + k0 + kl], red[tid]);
    }
}

// ---------------- tail kernels --------------------------------------------------
__global__ void colw_x_kernel(){
    int b = blockIdx.x;
    int ks = blockIdx.y * 128;
    int j = threadIdx.x;
    const __half* xb = g_x16 + ((size_t)b * L_ + ks) * D_;
    const float* cw = g_colw + b * L_ + ks;
    float s = 0.f;
#pragma unroll 4
    for (int kk = 0; kk < 128; kk++)
        s += cw[kk] * __half2float(xb[(size_t)kk * D_ + j]);
    atomicAdd(&g_t[b * D_ + j], s);
}

__global__ void final_kernel(const float* __restrict__ Wv, float* __restrict__ out){
    int warp = (blockIdx.x * blockDim.x + threadIdx.x) >> 5;
    int lane = threadIdx.x & 31;
    int b = warp >> 9;
    int d = warp & 511;
    const float* wr = Wv + (size_t)d * D_;
    const float* tr = g_t + b * D_;
    float s = 0.f;
    for (int j = lane; j < D_; j += 32) s += wr[j] * tr[j];
#pragma unroll
    for (int o = 16; o; o >>= 1) s += __shfl_down_sync(0xffffffffu, s, o);
    if (lane == 0) out[b * D_ + d] = s;
}

// ---------------- launch ----------------------------------------------------------
extern "C" void kernel_launch(void* const* d_in, const int* in_sizes, int n_in,
                              void* d_out, int out_size){
    const float* x   = (const float*)d_in[0];
    const float* Wq  = (const float*)d_in[1];
    const float* Wk  = (const float*)d_in[2];
    const float* Wv  = (const float*)d_in[3];
    const int*  lens = (const int*)d_in[4];
    float* out = (float*)d_out;

    __half *x16, *wq16, *wk16, *qp, *kp;
    float *cwp;
    cudaGetSymbolAddress((void**)&x16,  g_x16);
    cudaGetSymbolAddress((void**)&wq16, g_Wq16);
    cudaGetSymbolAddress((void**)&wk16, g_Wk16);
    cudaGetSymbolAddress((void**)&qp,   g_Q);
    cudaGetSymbolAddress((void**)&kp,   g_K);
    cudaGetSymbolAddress((void**)&cwp,  g_colw);

    cudaFuncSetAttribute(proj_hmma,   cudaFuncAttributeMaxDynamicSharedMemorySize, PJ_SMEM);
    cudaFuncSetAttribute(scores_hmma, cudaFuncAttributeMaxDynamicSharedMemorySize, SC_SMEM);

    prep_kernel<<<8192, 256>>>(x, Wq, Wk);

    proj_hmma<<<dim3(4, 128, 2), 256, PJ_SMEM>>>(x16, wq16, wk16, qp, kp);

    scores_hmma<<<dim3(32, 32), 512, SC_SMEM>>>(qp, kp, lens, cwp);

    colw_x_kernel<<<dim3(4, 32), 512>>>();
    final_kernel<<<256, 256>>>(Wv, out);
}

// round 7
// speedup vs baseline: 1.1493x; 1.1493x over previous
#include <cuda_runtime.h>
#include <cuda_fp16.h>
#include <stdint.h>

#define B_ 4
#define L_ 4096
#define D_ 512
#define M_ (B_*L_)

// ---------------- device scratch ---------------------------------------------
__device__ __half g_x16[(size_t)M_*D_];
__device__ __half g_Wq16[D_*D_], g_Wk16[D_*D_];
__device__ __half g_Q[(size_t)M_*D_], g_K[(size_t)M_*D_];
__device__ float g_colw[B_*L_];
__device__ float g_t[B_*D_];

// ---------------- helpers ----------------------------------------------------
#define SWZ(o) ((o) ^ ((((uint32_t)(o))>>3)&0x70u))

__device__ __forceinline__ uint32_t smem_u32(const void* p){
    return (uint32_t)__cvta_generic_to_shared(p);
}
__device__ __forceinline__ void ldsm4(uint32_t* r, uint32_t a){
    asm volatile("ldmatrix.sync.aligned.m8n8.x4.shared.b16 {%0,%1,%2,%3}, [%4];"
        : "=r"(r[0]), "=r"(r[1]), "=r"(r[2]), "=r"(r[3]) : "r"(a));
}
__device__ __forceinline__ void mma16816(float* d, const uint32_t* a, uint32_t b0, uint32_t b1){
    asm volatile("mma.sync.aligned.m16n8k16.row.col.f32.f16.f16.f32 "
        "{%0,%1,%2,%3}, {%4,%5,%6,%7}, {%8,%9}, {%0,%1,%2,%3};"
        : "+f"(d[0]), "+f"(d[1]), "+f"(d[2]), "+f"(d[3])
        : "r"(a[0]), "r"(a[1]), "r"(a[2]), "r"(a[3]), "r"(b0), "r"(b1));
}
__device__ __forceinline__ void mma16816h(uint32_t* d, const uint32_t* a, uint32_t b0, uint32_t b1){
    asm volatile("mma.sync.aligned.m16n8k16.row.col.f16.f16.f16.f16 "
        "{%0,%1}, {%2,%3,%4,%5}, {%6,%7}, {%0,%1};"
        : "+r"(d[0]), "+r"(d[1])
        : "r"(a[0]), "r"(a[1]), "r"(a[2]), "r"(a[3]), "r"(b0), "r"(b1));
}
__device__ __forceinline__ void cpa16(uint32_t s, const void* g){
    asm volatile("cp.async.cg.shared.global [%0], [%1], 16;" :: "r"(s), "l"(g) : "memory");
}
#define CP_COMMIT() asm volatile("cp.async.commit_group;" ::: "memory")
#define CP_WAIT(n)  asm volatile("cp.async.wait_group %0;" :: "n"(n) : "memory")

// packed subtile offset: 64 rows x 32 halfs stored as 32 x 128B smem rows
__device__ __forceinline__ uint32_t pko(int r, int seg){
    return ((uint32_t)(r>>1)<<7) + ((uint32_t)(r&1)<<6) + (uint32_t)seg*16;
}

// ---------------- prep (convert x, Wq, Wk; zero accumulators) ------------------
__global__ void prep_kernel(const float* __restrict__ x,
                            const float* __restrict__ Wq,
                            const float* __restrict__ Wk){
    int i = blockIdx.x*256 + threadIdx.x;       // 0 .. 2M-1 (float4 index of x)
    float4 v = ((const float4*)x)[i];
    ((__half2*)g_x16)[i*2]   = __floats2half2_rn(v.x, v.y);
    ((__half2*)g_x16)[i*2+1] = __floats2half2_rn(v.z, v.w);
    if (i < D_*D_/4){
        float4 a = ((const float4*)Wq)[i];
        float4 b = ((const float4*)Wk)[i];
        ((__half2*)g_Wq16)[i*2]   = __floats2half2_rn(a.x, a.y);
        ((__half2*)g_Wq16)[i*2+1] = __floats2half2_rn(a.z, a.w);
        ((__half2*)g_Wk16)[i*2]   = __floats2half2_rn(b.x, b.y);
        ((__half2*)g_Wk16)[i*2+1] = __floats2half2_rn(b.z, b.w);
    }
    if (i < B_*L_) g_colw[i] = 0.f;
    if (i < B_*D_) g_t[i] = 0.f;
}

// ---------------- projection GEMM (HMMA) ----------------------------------------
#define PJ_STAGE 32768
#define PJ_SMEM  (2*PJ_STAGE)

__device__ __forceinline__ void pj_load(const __half* __restrict__ A,
                                        const __half* __restrict__ W,
                                        int m0, int n0, int kc, uint32_t sdst, int tid){
#pragma unroll
    for (int i = 0; i < 8; i++){
        int lin = i*256 + tid;
        int sub = lin >> 9, row = (lin >> 3) & 63, sec = lin & 7;
        const __half* src;
        if (sub < 2) src = A + (size_t)(m0 + sub*64 + row)*D_ + kc + sec*8;
        else         src = W + (size_t)(n0 + (sub-2)*64 + row)*D_ + kc + sec*8;
        cpa16(sdst + sub*8192 + SWZ(row*128 + sec*16), src);
    }
}

__global__ __launch_bounds__(256, 1)
void proj_hmma(const __half* __restrict__ A,
               const __half* __restrict__ W0, const __half* __restrict__ W1,
               __half* __restrict__ C0, __half* __restrict__ C1){
    extern __shared__ __align__(1024) char sm[];
    const __half* W = blockIdx.z ? W1 : W0;
    __half* C = blockIdx.z ? C1 : C0;
    const int tid = threadIdx.x, wid = tid >> 5, lane = tid & 31;
    const int m0 = blockIdx.y * 128, n0 = blockIdx.x * 128;
    const uint32_t sb = smem_u32(sm);

    const int mw = (wid & 3) * 32, nw = (wid >> 2) * 64;
    const int a_r = lane & 15, a_s = (lane >> 4) * 16;
    const int b_n = (lane & 7) + ((lane >> 4) << 3);
    const int b_s = ((lane >> 3) & 1) * 16;

    float acc[2][8][4];
#pragma unroll
    for (int i = 0; i < 2; i++)
#pragma unroll
        for (int j = 0; j < 8; j++)
#pragma unroll
            for (int v = 0; v < 4; v++) acc[i][j][v] = 0.f;

    pj_load(A, W, m0, n0, 0, sb, tid); CP_COMMIT();

    for (int c = 0; c < 8; c++){
        if (c < 7){ pj_load(A, W, m0, n0, (c+1)*64, sb + ((c+1)&1)*PJ_STAGE, tid);
                    CP_COMMIT(); CP_WAIT(1); }
        else      { CP_WAIT(0); }
        __syncthreads();
        uint32_t st = sb + (c & 1) * PJ_STAGE;
#pragma unroll
        for (int ks = 0; ks < 4; ks++){
            int kb = ks * 32;
            uint32_t A0[4], A1[4], Bv[4];
            {
                int r0 = mw + a_r, r1 = mw + 16 + a_r;
                ldsm4(A0, st + (r0 >> 6)*8192 + SWZ((r0 & 63)*128 + kb + a_s));
                ldsm4(A1, st + (r1 >> 6)*8192 + SWZ((r1 & 63)*128 + kb + a_s));
            }
#pragma unroll
            for (int nb = 0; nb < 4; nb++){
                int n = nw + nb*16 + b_n;
                ldsm4(Bv, st + (2 + (n >> 6))*8192 + SWZ((n & 63)*128 + kb + b_s));
                mma16816(acc[0][nb*2],   A0, Bv[0], Bv[1]);
                mma16816(acc[0][nb*2+1], A0, Bv[2], Bv[3]);
                mma16816(acc[1][nb*2],   A1, Bv[0], Bv[1]);
                mma16816(acc[1][nb*2+1], A1, Bv[2], Bv[3]);
            }
        }
        __syncthreads();
    }

    const int er = lane >> 2, ec = (lane & 3) * 2;
#pragma unroll
    for (int mt = 0; mt < 2; mt++)
#pragma unroll
        for (int n8 = 0; n8 < 8; n8++){
            size_t r = (size_t)(m0 + mw + mt*16 + er);
            int col = n0 + nw + n8*8 + ec;
            *(__half2*)&C[r*D_ + col] =
                __floats2half2_rn(acc[mt][n8][0], acc[mt][n8][1]);
            *(__half2*)&C[(r+8)*D_ + col] =
                __floats2half2_rn(acc[mt][n8][2], acc[mt][n8][3]);
        }
}

// ---------------- fused scores: 256 threads, 2 CTAs/SM ---------------------------
// Block tile 128q x 64k x 4b; warp = (batch, q-half) -> 64q x 64k, fp16 acc.
// Stage (kc=32): Q 8 subtiles + K 4 subtiles of 64x32 halfs = 48KB, double-buffered.
#define ST_STAGE 49152
#define RED_OFF  (2*ST_STAGE)               // 98304
#define SC_SMEM  (RED_OFF + 1024)           // 99328 -> 2 CTAs/SM
#define PQS 72                              // park q-stride in halfs (144B rows)

__device__ __forceinline__ void sc_load(const __half* __restrict__ Q,
                                        const __half* __restrict__ K,
                                        int q0, int k0, int kc, uint32_t sdst, int tid){
#pragma unroll
    for (int i = 0; i < 12; i++){
        int lin = i*256 + tid;                   // 0..3071
        int sub = lin >> 8, rem = lin & 255;
        int r = rem >> 2, seg = rem & 3;
        const __half* src;
        if (sub < 8){
            int b = sub >> 1;
            src = Q + (size_t)(b*L_ + q0 + (sub & 1)*64 + r)*D_ + kc + seg*8;
        } else {
            int b = sub - 8;
            src = K + (size_t)(b*L_ + k0 + r)*D_ + kc + seg*8;
        }
        cpa16(sdst + sub*4096 + SWZ(pko(r, seg)), src);
    }
}

__global__ __launch_bounds__(256, 2)
void scores_hmma(const __half* __restrict__ Q, const __half* __restrict__ K,
                 const int* __restrict__ lens, float* __restrict__ colw){
    extern __shared__ __align__(1024) char sm[];
    const int tid = threadIdx.x, wid = tid >> 5, lane = tid & 31;
    const int q0 = blockIdx.y * 128, k0 = blockIdx.x * 64;
    const uint32_t sb = smem_u32(sm);
    float* red = (float*)(sm + RED_OFF);
    red[tid] = 0.f;

    const int b  = wid & 3;                      // batch
    const int wq = wid >> 2;                     // q half (64 rows)
    const int a_r = lane & 15, a_hi = lane >> 4;
    const int b_n = (lane & 7) + ((lane >> 4) << 3);
    const int b_hi = (lane >> 3) & 1;
    const int er = lane >> 2, ec = (lane & 3) * 2;

    uint32_t acc[4][8][2];                       // fp16x2 accumulators
#pragma unroll
    for (int i = 0; i < 4; i++)
#pragma unroll
        for (int j = 0; j < 8; j++){ acc[i][j][0] = 0u; acc[i][j][1] = 0u; }

    sc_load(Q, K, q0, k0, 0, sb, tid); CP_COMMIT();

    for (int c = 0; c < 16; c++){
        if (c < 15){ sc_load(Q, K, q0, k0, (c+1)*32, sb + ((c+1)&1)*ST_STAGE, tid);
                     CP_COMMIT(); CP_WAIT(1); }
        else       { CP_WAIT(0); }
        __syncthreads();
        uint32_t st = sb + (c & 1)*ST_STAGE;
        uint32_t qt = st + (b*2 + wq)*4096;
        uint32_t kt = st + (8 + b)*4096;
#pragma unroll
        for (int ks = 0; ks < 2; ks++){
            uint32_t Af[4][4];
#pragma unroll
            for (int mt = 0; mt < 4; mt++)
                ldsm4(Af[mt], qt + SWZ(pko(mt*16 + a_r, ks*2 + a_hi)));
#pragma unroll
            for (int nb = 0; nb < 4; nb++){
                uint32_t Bv[4];
                ldsm4(Bv, kt + SWZ(pko(nb*16 + b_n, ks*2 + b_hi)));
#pragma unroll
                for (int mt = 0; mt < 4; mt++){
                    mma16816h(acc[mt][nb*2],   Af[mt], Bv[0], Bv[1]);
                    mma16816h(acc[mt][nb*2+1], Af[mt], Bv[2], Bv[3]);
                }
            }
        }
        __syncthreads();
    }

    // ---------------- park fp16 S (q-major, stride PQS) -------------------------
    __half* Pk = (__half*)sm;                    // [b][q(128)][k(64)] stride PQS
#pragma unroll
    for (int mt = 0; mt < 4; mt++)
#pragma unroll
        for (int t = 0; t < 8; t++)
#pragma unroll
            for (int rh = 0; rh < 2; rh++){
                int qrow = wq*64 + mt*16 + rh*8 + er;
                int kcol = t*8 + ec;
                *(uint32_t*)&Pk[(size_t)b*128*PQS + (size_t)qrow*PQS + kcol] = acc[mt][t][rh];
            }
    __syncthreads();

    // ---------------- batch softmax + masked q reduction -------------------------
    const int le0 = lens[0], le1 = lens[1], le2 = lens[2], le3 = lens[3];
    const int kp = tid & 31;                     // k pair index (2 k's)
    const int qb8 = tid >> 5;                    // 0..7
    float2 a0 = {0.f,0.f}, a1 = {0.f,0.f}, a2 = {0.f,0.f}, a3 = {0.f,0.f};
#pragma unroll 2
    for (int it = 0; it < 16; it++){
        int q = it*8 + qb8;
        float2 s0 = __half22float2(*(__half2*)&Pk[0*128*PQS + q*PQS + kp*2]);
        float2 s1 = __half22float2(*(__half2*)&Pk[1*128*PQS + q*PQS + kp*2]);
        float2 s2 = __half22float2(*(__half2*)&Pk[2*128*PQS + q*PQS + kp*2]);
        float2 s3 = __half22float2(*(__half2*)&Pk[3*128*PQS + q*PQS + kp*2]);
        float e0x = __expf(s0.x*0.0625f), e0y = __expf(s0.y*0.0625f);
        float e1x = __expf(s1.x*0.0625f), e1y = __expf(s1.y*0.0625f);
        float e2x = __expf(s2.x*0.0625f), e2y = __expf(s2.y*0.0625f);
        float e3x = __expf(s3.x*0.0625f), e3y = __expf(s3.y*0.0625f);
        float ix = 1.f/(e0x+e1x+e2x+e3x), iy = 1.f/(e0y+e1y+e2y+e3y);
        int qg = q0 + q;
        if (qg < le0){ a0.x += e0x*ix; a0.y += e0y*iy; }
        if (qg < le1){ a1.x += e1x*ix; a1.y += e1y*iy; }
        if (qg < le2){ a2.x += e2x*ix; a2.y += e2y*iy; }
        if (qg < le3){ a3.x += e3x*ix; a3.y += e3y*iy; }
    }
    atomicAdd(&red[(kp*2  )*4 + 0], a0.x); atomicAdd(&red[(kp*2+1)*4 + 0], a0.y);
    atomicAdd(&red[(kp*2  )*4 + 1], a1.x); atomicAdd(&red[(kp*2+1)*4 + 1], a1.y);
    atomicAdd(&red[(kp*2  )*4 + 2], a2.x); atomicAdd(&red[(kp*2+1)*4 + 2], a2.y);
    atomicAdd(&red[(kp*2  )*4 + 3], a3.x); atomicAdd(&red[(kp*2+1)*4 + 3], a3.y);
    __syncthreads();

    {
        int kl = tid >> 2, bb = tid & 3;
        atomicAdd(&colw[bb*L_ + k0 + kl], red[tid]);
    }
}

// ---------------- tail kernels ----------------------------------------------------
__global__ void colw_x_kernel(){
    int b = blockIdx.x;
    int ks = blockIdx.y * 32;
    int j = threadIdx.x;
    const __half* xb = g_x16 + ((size_t)b * L_ + ks) * D_;
    const float* cw = g_colw + b * L_ + ks;
    float s = 0.f;
#pragma unroll 8
    for (int kk = 0; kk < 32; kk++)
        s += cw[kk] * __half2float(xb[(size_t)kk * D_ + j]);
    atomicAdd(&g_t[b * D_ + j], s);
}

__global__ void final_kernel(const float* __restrict__ Wv, float* __restrict__ out){
    int warp = (blockIdx.x * blockDim.x + threadIdx.x) >> 5;
    int lane = threadIdx.x & 31;
    int b = warp >> 9;
    int d = warp & 511;
    const float* wr = Wv + (size_t)d * D_;
    const float* tr = g_t + b * D_;
    float s = 0.f;
    for (int j = lane; j < D_; j += 32) s += wr[j] * tr[j];
#pragma unroll
    for (int o = 16; o; o >>= 1) s += __shfl_down_sync(0xffffffffu, s, o);
    if (lane == 0) out[b * D_ + d] = s;
}

// ---------------- launch ------------------------------------------------------------
extern "C" void kernel_launch(void* const* d_in, const int* in_sizes, int n_in,
                              void* d_out, int out_size){
    const float* x   = (const float*)d_in[0];
    const float* Wq  = (const float*)d_in[1];
    const float* Wk  = (const float*)d_in[2];
    const float* Wv  = (const float*)d_in[3];
    const int*  lens = (const int*)d_in[4];
    float* out = (float*)d_out;

    __half *x16, *wq16, *wk16, *qp, *kp;
    float *cwp;
    cudaGetSymbolAddress((void**)&x16,  g_x16);
    cudaGetSymbolAddress((void**)&wq16, g_Wq16);
    cudaGetSymbolAddress((void**)&wk16, g_Wk16);
    cudaGetSymbolAddress((void**)&qp,   g_Q);
    cudaGetSymbolAddress((void**)&kp,   g_K);
    cudaGetSymbolAddress((void**)&cwp,  g_colw);

    cudaFuncSetAttribute(proj_hmma,   cudaFuncAttributeMaxDynamicSharedMemorySize, PJ_SMEM);
    cudaFuncSetAttribute(scores_hmma, cudaFuncAttributeMaxDynamicSharedMemorySize, SC_SMEM);

    prep_kernel<<<8192, 256>>>(x, Wq, Wk);

    proj_hmma<<<dim3(4, 128, 2), 256, PJ_SMEM>>>(x16, wq16, wk16, qp, kp);

    scores_hmma<<<dim3(64, 32), 256, SC_SMEM>>>(qp, kp, lens, cwp);

    colw_x_kernel<<<dim3(4, 128), 512>>>();
    final_kernel<<<256, 256>>>(Wv, out);
}

// round 8
// speedup vs baseline: 1.2888x; 1.1213x over previous
#include <cuda_runtime.h>
#include <cuda_fp16.h>
#include <stdint.h>

#define B_ 4
#define L_ 4096
#define D_ 512
#define M_ (B_*L_)

// ---------------- device scratch ---------------------------------------------
__device__ __half g_x16[(size_t)M_*D_];
__device__ __half g_Wq16[D_*D_], g_Wk16[D_*D_];
__device__ __half g_Q[(size_t)M_*D_], g_K[(size_t)M_*D_];
__device__ float g_colw[B_*L_];
__device__ float g_t[B_*D_];

// ---------------- helpers ----------------------------------------------------
#define SWZ(o) ((o) ^ ((((uint32_t)(o))>>3)&0x70u))

__device__ __forceinline__ uint32_t smem_u32(const void* p){
    return (uint32_t)__cvta_generic_to_shared(p);
}
__device__ __forceinline__ void ldsm4(uint32_t* r, uint32_t a){
    asm volatile("ldmatrix.sync.aligned.m8n8.x4.shared.b16 {%0,%1,%2,%3}, [%4];"
        : "=r"(r[0]), "=r"(r[1]), "=r"(r[2]), "=r"(r[3]) : "r"(a));
}
__device__ __forceinline__ void mma16816(float* d, const uint32_t* a, uint32_t b0, uint32_t b1){
    asm volatile("mma.sync.aligned.m16n8k16.row.col.f32.f16.f16.f32 "
        "{%0,%1,%2,%3}, {%4,%5,%6,%7}, {%8,%9}, {%0,%1,%2,%3};"
        : "+f"(d[0]), "+f"(d[1]), "+f"(d[2]), "+f"(d[3])
        : "r"(a[0]), "r"(a[1]), "r"(a[2]), "r"(a[3]), "r"(b0), "r"(b1));
}
__device__ __forceinline__ void mma16816h(uint32_t* d, const uint32_t* a, uint32_t b0, uint32_t b1){
    asm volatile("mma.sync.aligned.m16n8k16.row.col.f16.f16.f16.f16 "
        "{%0,%1}, {%2,%3,%4,%5}, {%6,%7}, {%0,%1};"
        : "+r"(d[0]), "+r"(d[1])
        : "r"(a[0]), "r"(a[1]), "r"(a[2]), "r"(a[3]), "r"(b0), "r"(b1));
}
__device__ __forceinline__ void cpa16(uint32_t s, const void* g){
    asm volatile("cp.async.cg.shared.global [%0], [%1], 16;" :: "r"(s), "l"(g) : "memory");
}
#define CP_COMMIT() asm volatile("cp.async.commit_group;" ::: "memory")
#define CP_WAIT(n)  asm volatile("cp.async.wait_group %0;" :: "n"(n) : "memory")
__device__ __forceinline__ void barp(int id){
    asm volatile("bar.sync %0, 64;" :: "r"(id) : "memory");
}

// packed subtile offset: 64 rows x 32 halfs stored as 32 x 128B smem rows
__device__ __forceinline__ uint32_t pko(int r, int seg){
    return ((uint32_t)(r>>1)<<7) + ((uint32_t)(r&1)<<6) + (uint32_t)seg*16;
}

// ---------------- prep (convert x, Wq, Wk; zero accumulators) ------------------
__global__ void prep_kernel(const float* __restrict__ x,
                            const float* __restrict__ Wq,
                            const float* __restrict__ Wk){
    int i = blockIdx.x*256 + threadIdx.x;
    float4 v = ((const float4*)x)[i];
    ((__half2*)g_x16)[i*2]   = __floats2half2_rn(v.x, v.y);
    ((__half2*)g_x16)[i*2+1] = __floats2half2_rn(v.z, v.w);
    if (i < D_*D_/4){
        float4 a = ((const float4*)Wq)[i];
        float4 b = ((const float4*)Wk)[i];
        ((__half2*)g_Wq16)[i*2]   = __floats2half2_rn(a.x, a.y);
        ((__half2*)g_Wq16)[i*2+1] = __floats2half2_rn(a.z, a.w);
        ((__half2*)g_Wk16)[i*2]   = __floats2half2_rn(b.x, b.y);
        ((__half2*)g_Wk16)[i*2+1] = __floats2half2_rn(b.z, b.w);
    }
    if (i < B_*L_) g_colw[i] = 0.f;
    if (i < B_*D_) g_t[i] = 0.f;
}

// ---------------- projection GEMM (HMMA) ----------------------------------------
#define PJ_STAGE 32768
#define PJ_SMEM  (2*PJ_STAGE)

__device__ __forceinline__ void pj_load(const __half* __restrict__ A,
                                        const __half* __restrict__ W,
                                        int m0, int n0, int kc, uint32_t sdst, int tid){
#pragma unroll
    for (int i = 0; i < 8; i++){
        int lin = i*256 + tid;
        int sub = lin >> 9, row = (lin >> 3) & 63, sec = lin & 7;
        const __half* src;
        if (sub < 2) src = A + (size_t)(m0 + sub*64 + row)*D_ + kc + sec*8;
        else         src = W + (size_t)(n0 + (sub-2)*64 + row)*D_ + kc + sec*8;
        cpa16(sdst + sub*8192 + SWZ(row*128 + sec*16), src);
    }
}

__global__ __launch_bounds__(256, 2)
void proj_hmma(const __half* __restrict__ A,
               const __half* __restrict__ W0, const __half* __restrict__ W1,
               __half* __restrict__ C0, __half* __restrict__ C1){
    extern __shared__ __align__(1024) char sm[];
    const __half* W = blockIdx.z ? W1 : W0;
    __half* C = blockIdx.z ? C1 : C0;
    const int tid = threadIdx.x, wid = tid >> 5, lane = tid & 31;
    const int m0 = blockIdx.y * 128, n0 = blockIdx.x * 128;
    const uint32_t sb = smem_u32(sm);

    const int mw = (wid & 3) * 32, nw = (wid >> 2) * 64;
    const int a_r = lane & 15, a_s = (lane >> 4) * 16;
    const int b_n = (lane & 7) + ((lane >> 4) << 3);
    const int b_s = ((lane >> 3) & 1) * 16;

    float acc[2][8][4];
#pragma unroll
    for (int i = 0; i < 2; i++)
#pragma unroll
        for (int j = 0; j < 8; j++)
#pragma unroll
            for (int v = 0; v < 4; v++) acc[i][j][v] = 0.f;

    pj_load(A, W, m0, n0, 0, sb, tid); CP_COMMIT();

    for (int c = 0; c < 8; c++){
        if (c < 7){ pj_load(A, W, m0, n0, (c+1)*64, sb + ((c+1)&1)*PJ_STAGE, tid);
                    CP_COMMIT(); CP_WAIT(1); }
        else      { CP_WAIT(0); }
        __syncthreads();
        uint32_t st = sb + (c & 1) * PJ_STAGE;
#pragma unroll
        for (int ks = 0; ks < 4; ks++){
            int kb = ks * 32;
            uint32_t A0[4], A1[4], Bv[4];
            {
                int r0 = mw + a_r, r1 = mw + 16 + a_r;
                ldsm4(A0, st + (r0 >> 6)*8192 + SWZ((r0 & 63)*128 + kb + a_s));
                ldsm4(A1, st + (r1 >> 6)*8192 + SWZ((r1 & 63)*128 + kb + a_s));
            }
#pragma unroll
            for (int nb = 0; nb < 4; nb++){
                int n = nw + nb*16 + b_n;
                ldsm4(Bv, st + (2 + (n >> 6))*8192 + SWZ((n & 63)*128 + kb + b_s));
                mma16816(acc[0][nb*2],   A0, Bv[0], Bv[1]);
                mma16816(acc[0][nb*2+1], A0, Bv[2], Bv[3]);
                mma16816(acc[1][nb*2],   A1, Bv[0], Bv[1]);
                mma16816(acc[1][nb*2+1], A1, Bv[2], Bv[3]);
            }
        }
        __syncthreads();
    }

    const int er = lane >> 2, ec = (lane & 3) * 2;
#pragma unroll
    for (int mt = 0; mt < 2; mt++)
#pragma unroll
        for (int n8 = 0; n8 < 8; n8++){
            size_t r = (size_t)(m0 + mw + mt*16 + er);
            int col = n0 + nw + n8*8 + ec;
            *(__half2*)&C[r*D_ + col] =
                __floats2half2_rn(acc[mt][n8][0], acc[mt][n8][1]);
            *(__half2*)&C[(r+8)*D_ + col] =
                __floats2half2_rn(acc[mt][n8][2], acc[mt][n8][3]);
        }
}

// ---------------- fused scores: pair-local pipelines, 2 CTAs/SM -------------------
// Block 128q x 64k x 4b; warp (b, wq) = 64q x 64k fp16 acc.
// Pair (b,0)+(b,1) shares only K subtile b -> named barrier per pair, no lockstep.
#define ST_STAGE 49152
#define RED_OFF  (2*ST_STAGE)               // 98304
#define SC_SMEM  (RED_OFF + 1024)           // 99328 -> 2 CTAs/SM
#define PQS 72

// per-warp load of its chunk share (Q subtile 2b+wq, K subtile 8+b half wq)
__device__ __forceinline__ void sc_load_w(const __half* __restrict__ Q,
                                          const __half* __restrict__ K,
                                          int q0, int k0, int kc, uint32_t sdst,
                                          int b, int wq, int lane){
    const __half* qsrc = Q + (size_t)(b*L_ + q0 + wq*64)*D_ + kc;
    uint32_t qdst = sdst + (2*b + wq)*4096;
#pragma unroll
    for (int i = 0; i < 8; i++){
        int idx = i*32 + lane;            // 0..255
        int r = idx >> 2, seg = idx & 3;
        cpa16(qdst + SWZ(pko(r, seg)), qsrc + (size_t)r*D_ + seg*8);
    }
    const __half* ksrc = K + (size_t)(b*L_ + k0 + wq*32)*D_ + kc;
    uint32_t kdst = sdst + (8 + b)*4096;
#pragma unroll
    for (int i = 0; i < 4; i++){
        int idx = i*32 + lane;            // 0..127
        int r = idx >> 2, seg = idx & 3;
        cpa16(kdst + SWZ(pko(r + wq*32, seg)), ksrc + (size_t)r*D_ + seg*8);
    }
}

__global__ __launch_bounds__(256, 2)
void scores_hmma(const __half* __restrict__ Q, const __half* __restrict__ K,
                 const int* __restrict__ lens, float* __restrict__ colw){
    extern __shared__ __align__(1024) char sm[];
    const int tid = threadIdx.x, wid = tid >> 5, lane = tid & 31;
    const int q0 = blockIdx.y * 128, k0 = blockIdx.x * 64;
    const uint32_t sb = smem_u32(sm);
    float* red = (float*)(sm + RED_OFF);
    red[tid] = 0.f;

    const int b  = wid & 3;
    const int wq = wid >> 2;
    const int bar_id = 1 + b;
    const int a_r = lane & 15, a_hi = lane >> 4;
    const int b_n = (lane & 7) + ((lane >> 4) << 3);
    const int b_hi = (lane >> 3) & 1;
    const int er = lane >> 2, ec = (lane & 3) * 2;

    uint32_t acc[4][8][2];
#pragma unroll
    for (int i = 0; i < 4; i++)
#pragma unroll
        for (int j = 0; j < 8; j++){ acc[i][j][0] = 0u; acc[i][j][1] = 0u; }

    sc_load_w(Q, K, q0, k0, 0, sb, b, wq, lane); CP_COMMIT();

    for (int c = 0; c < 16; c++){
        if (c < 15){ sc_load_w(Q, K, q0, k0, (c+1)*32, sb + ((c+1)&1)*ST_STAGE, b, wq, lane);
                     CP_COMMIT(); CP_WAIT(1); }
        else       { CP_WAIT(0); }
        barp(bar_id);                         // pair's chunk c fully in smem
        uint32_t st = sb + (c & 1)*ST_STAGE;
        uint32_t qt = st + (b*2 + wq)*4096;
        uint32_t kt = st + (8 + b)*4096;
#pragma unroll
        for (int ks = 0; ks < 2; ks++){
            uint32_t Af[4][4];
#pragma unroll
            for (int mt = 0; mt < 4; mt++)
                ldsm4(Af[mt], qt + SWZ(pko(mt*16 + a_r, ks*2 + a_hi)));
#pragma unroll
            for (int nb = 0; nb < 4; nb++){
                uint32_t Bv[4];
                ldsm4(Bv, kt + SWZ(pko(nb*16 + b_n, ks*2 + b_hi)));
#pragma unroll
                for (int mt = 0; mt < 4; mt++){
                    mma16816h(acc[mt][nb*2],   Af[mt], Bv[0], Bv[1]);
                    mma16816h(acc[mt][nb*2+1], Af[mt], Bv[2], Bv[3]);
                }
            }
        }
        barp(bar_id);                         // pair done reading buffer c
    }
    __syncthreads();                          // all pairs done; stages reusable as park

    // ---------------- park fp16 S (q-major, stride PQS) -------------------------
    __half* Pk = (__half*)sm;
#pragma unroll
    for (int mt = 0; mt < 4; mt++)
#pragma unroll
        for (int t = 0; t < 8; t++)
#pragma unroll
            for (int rh = 0; rh < 2; rh++){
                int qrow = wq*64 + mt*16 + rh*8 + er;
                int kcol = t*8 + ec;
                *(uint32_t*)&Pk[(size_t)b*128*PQS + (size_t)qrow*PQS + kcol] = acc[mt][t][rh];
            }
    __syncthreads();

    // ---------------- batch softmax + masked q reduction -------------------------
    const int le0 = lens[0], le1 = lens[1], le2 = lens[2], le3 = lens[3];
    const int kp = tid & 31;
    const int qb8 = tid >> 5;
    float2 a0 = {0.f,0.f}, a1 = {0.f,0.f}, a2 = {0.f,0.f}, a3 = {0.f,0.f};
#pragma unroll 2
    for (int it = 0; it < 16; it++){
        int q = it*8 + qb8;
        float2 s0 = __half22float2(*(__half2*)&Pk[0*128*PQS + q*PQS + kp*2]);
        float2 s1 = __half22float2(*(__half2*)&Pk[1*128*PQS + q*PQS + kp*2]);
        float2 s2 = __half22float2(*(__half2*)&Pk[2*128*PQS + q*PQS + kp*2]);
        float2 s3 = __half22float2(*(__half2*)&Pk[3*128*PQS + q*PQS + kp*2]);
        float e0x = __expf(s0.x*0.0625f), e0y = __expf(s0.y*0.0625f);
        float e1x = __expf(s1.x*0.0625f), e1y = __expf(s1.y*0.0625f);
        float e2x = __expf(s2.x*0.0625f), e2y = __expf(s2.y*0.0625f);
        float e3x = __expf(s3.x*0.0625f), e3y = __expf(s3.y*0.0625f);
        float ix = 1.f/(e0x+e1x+e2x+e3x), iy = 1.f/(e0y+e1y+e2y+e3y);
        int qg = q0 + q;
        if (qg < le0){ a0.x += e0x*ix; a0.y += e0y*iy; }
        if (qg < le1){ a1.x += e1x*ix; a1.y += e1y*iy; }
        if (qg < le2){ a2.x += e2x*ix; a2.y += e2y*iy; }
        if (qg < le3){ a3.x += e3x*ix; a3.y += e3y*iy; }
    }
    atomicAdd(&red[(kp*2  )*4 + 0], a0.x); atomicAdd(&red[(kp*2+1)*4 + 0], a0.y);
    atomicAdd(&red[(kp*2  )*4 + 1], a1.x); atomicAdd(&red[(kp*2+1)*4 + 1], a1.y);
    atomicAdd(&red[(kp*2  )*4 + 2], a2.x); atomicAdd(&red[(kp*2+1)*4 + 2], a2.y);
    atomicAdd(&red[(kp*2  )*4 + 3], a3.x); atomicAdd(&red[(kp*2+1)*4 + 3], a3.y);
    __syncthreads();

    {
        int kl = tid >> 2, bb = tid & 3;
        atomicAdd(&colw[bb*L_ + k0 + kl], red[tid]);
    }
}

// ---------------- tail kernels ----------------------------------------------------
__global__ void colw_x_kernel(){
    int b = blockIdx.x;
    int ks = blockIdx.y * 32;
    int j = threadIdx.x;
    const __half* xb = g_x16 + ((size_t)b * L_ + ks) * D_;
    const float* cw = g_colw + b * L_ + ks;
    float s = 0.f;
#pragma unroll 8
    for (int kk = 0; kk < 32; kk++)
        s += cw[kk] * __half2float(xb[(size_t)kk * D_ + j]);
    atomicAdd(&g_t[b * D_ + j], s);
}

__global__ void final_kernel(const float* __restrict__ Wv, float* __restrict__ out){
    int warp = (blockIdx.x * blockDim.x + threadIdx.x) >> 5;
    int lane = threadIdx.x & 31;
    int b = warp >> 9;
    int d = warp & 511;
    const float* wr = Wv + (size_t)d * D_;
    const float* tr = g_t + b * D_;
    float s = 0.f;
    for (int j = lane; j < D_; j += 32) s += wr[j] * tr[j];
#pragma unroll
    for (int o = 16; o; o >>= 1) s += __shfl_down_sync(0xffffffffu, s, o);
    if (lane == 0) out[b * D_ + d] = s;
}

// ---------------- launch ------------------------------------------------------------
extern "C" void kernel_launch(void* const* d_in, const int* in_sizes, int n_in,
                              void* d_out, int out_size){
    const float* x   = (const float*)d_in[0];
    const float* Wq  = (const float*)d_in[1];
    const float* Wk  = (const float*)d_in[2];
    const float* Wv  = (const float*)d_in[3];
    const int*  lens = (const int*)d_in[4];
    float* out = (float*)d_out;

    __half *x16, *wq16, *wk16, *qp, *kp;
    float *cwp;
    cudaGetSymbolAddress((void**)&x16,  g_x16);
    cudaGetSymbolAddress((void**)&wq16, g_Wq16);
    cudaGetSymbolAddress((void**)&wk16, g_Wk16);
    cudaGetSymbolAddress((void**)&qp,   g_Q);
    cudaGetSymbolAddress((void**)&kp,   g_K);
    cudaGetSymbolAddress((void**)&cwp,  g_colw);

    cudaFuncSetAttribute(proj_hmma,   cudaFuncAttributeMaxDynamicSharedMemorySize, PJ_SMEM);
    cudaFuncSetAttribute(scores_hmma, cudaFuncAttributeMaxDynamicSharedMemorySize, SC_SMEM);

    prep_kernel<<<8192, 256>>>(x, Wq, Wk);

    proj_hmma<<<dim3(4, 128, 2), 256, PJ_SMEM>>>(x16, wq16, wk16, qp, kp);

    scores_hmma<<<dim3(64, 32), 256, SC_SMEM>>>(qp, kp, lens, cwp);

    colw_x_kernel<<<dim3(4, 128), 512>>>();
    final_kernel<<<256, 256>>>(Wv, out);
}